// round 6
// baseline (speedup 1.0000x reference)
#include <cuda_runtime.h>
#include <cuda_fp16.h>

#define NN 100000
#define EE 1600000
#define FIN 128
#define HID 64

// ---- scratch (static __device__ — no allocation) ----
__device__ __align__(16) __half2 g_h1h[NN * 32];  // h1, fp16, feature pairs
__device__ __align__(16) __half2 g_h2h[NN * 32];  // h2, fp16
__device__ __align__(16) float g_as1[NN * 4];
__device__ __align__(16) float g_ad1[NN * 4];
__device__ __align__(16) float g_agg1[NN * HID];
__device__ __align__(16) float g_as2[NN];
__device__ __align__(16) float g_ad2[NN];
__device__ int g_cnt[NN];    // degree by dst
__device__ int g_rs[NN];     // CSR row starts
__device__ int g_cur[NN];    // fill cursors
__device__ int g_srcs[EE];   // CSR: src per incident edge, grouped by dst

__device__ __forceinline__ float lrelu(float t) { return t > 0.f ? t : 0.2f * t; }

// ---------------- CSR build ----------------
__global__ void k_zero_cnt() {
    int i = blockIdx.x * blockDim.x + threadIdx.x;
    if (i < NN) g_cnt[i] = 0;
}

__global__ void k_hist(const int* __restrict__ ei) {
    int e = blockIdx.x * blockDim.x + threadIdx.x;
    if (e < EE) atomicAdd(&g_cnt[__ldg(&ei[EE + e])], 1);
}

// single-block full exclusive scan of g_cnt -> g_rs, g_cur (1024 threads, chunked)
__global__ void k_scan() {
    __shared__ int sh[32];
    int tid = threadIdx.x;
    int lane = tid & 31, w = tid >> 5;
    int run = 0;
    const int nchunks = (NN + 1023) / 1024;
    for (int c = 0; c < nchunks; c++) {
        int i = c * 1024 + tid;
        int v = (i < NN) ? g_cnt[i] : 0;
        int s = v;
#pragma unroll
        for (int off = 1; off < 32; off <<= 1) {
            int t = __shfl_up_sync(0xffffffffu, s, off);
            if (lane >= off) s += t;
        }
        if (lane == 31) sh[w] = s;
        __syncthreads();
        if (w == 0) {
            int t = sh[lane];
#pragma unroll
            for (int off = 1; off < 32; off <<= 1) {
                int u = __shfl_up_sync(0xffffffffu, t, off);
                if (lane >= off) t += u;
            }
            sh[lane] = t;
        }
        __syncthreads();
        int base = (w > 0) ? sh[w - 1] : 0;
        if (i < NN) {
            int r = run + base + s - v;
            g_rs[i] = r;
            g_cur[i] = r;
        }
        run += sh[31];
        __syncthreads();
    }
}

__global__ void k_fill(const int* __restrict__ ei) {
    int e = blockIdx.x * blockDim.x + threadIdx.x;
    if (e < EE) {
        int s = __ldg(&ei[e]);
        int d = __ldg(&ei[EE + e]);
        int p = atomicAdd(&g_cur[d], 1);
        g_srcs[p] = s;
    }
}

// ---------------- layer-1 GEMM: h1 = x @ W1 (fp16 out) + per-head attention dots ----------------
// Lane owns adjacent feature pair (2*lane, 2*lane+1); head = lane>>3.
__global__ void k_gemm1(const float* __restrict__ x, const float* __restrict__ W1,
                        const float* __restrict__ a_src, const float* __restrict__ a_dst) {
    __shared__ float2 Wsh[FIN * 32];
    int tid = threadIdx.x;
    for (int i = tid; i < FIN * 32; i += 256) Wsh[i] = ((const float2*)W1)[i];
    __syncthreads();

    int lane = tid & 31, w = tid >> 5;
    int r0 = (blockIdx.x * 8 + w) * 4;

    float xr[4][4];
#pragma unroll
    for (int i = 0; i < 4; i++)
#pragma unroll
        for (int j = 0; j < 4; j++)
            xr[i][j] = x[(r0 + i) * FIN + 32 * j + lane];

    float acc0[4] = {}, acc1[4] = {};
#pragma unroll
    for (int k = 0; k < FIN; k++) {
        float2 wv = Wsh[k * 32 + lane];
#pragma unroll
        for (int i = 0; i < 4; i++) {
            float xk = __shfl_sync(0xffffffffu, xr[i][k >> 5], k & 31);
            acc0[i] += xk * wv.x;
            acc1[i] += xk * wv.y;
        }
    }

    float s0 = __ldg(&a_src[2 * lane]), s1 = __ldg(&a_src[2 * lane + 1]);
    float d0 = __ldg(&a_dst[2 * lane]), d1 = __ldg(&a_dst[2 * lane + 1]);

#pragma unroll
    for (int i = 0; i < 4; i++) {
        int row = r0 + i;
        g_h1h[row * 32 + lane] = __floats2half2_rn(acc0[i], acc1[i]);
        float pa = acc0[i] * s0 + acc1[i] * s1;
        float pd = acc0[i] * d0 + acc1[i] * d1;
#pragma unroll
        for (int off = 4; off; off >>= 1) {
            pa += __shfl_xor_sync(0xffffffffu, pa, off);
            pd += __shfl_xor_sync(0xffffffffu, pd, off);
        }
        if ((lane & 7) == 0) {
            g_as1[row * 4 + (lane >> 3)] = pa;
            g_ad1[row * 4 + (lane >> 3)] = pd;
        }
    }
}

// ---------------- layer-1 gather aggregation: one warp per dst node ----------------
__global__ void k_agg1() {
    int n = blockIdx.x * 8 + (threadIdx.x >> 5);
    if (n >= NN) return;
    int lane = threadIdx.x & 31;
    int head = lane >> 3;

    int rs = g_rs[n];
    int deg = g_cnt[n];
    float adv = g_ad1[n * 4 + head];

    float ax = 0.f, ay = 0.f, den = 0.f;

    int j = 0;
    for (; j + 4 <= deg; j += 4) {
        int s0 = g_srcs[rs + j],     s1 = g_srcs[rs + j + 1];
        int s2 = g_srcs[rs + j + 2], s3 = g_srcs[rs + j + 3];
        float t0 = g_as1[s0 * 4 + head] + adv;
        float t1 = g_as1[s1 * 4 + head] + adv;
        float t2 = g_as1[s2 * 4 + head] + adv;
        float t3 = g_as1[s3 * 4 + head] + adv;
        float2 v0 = __half22float2(g_h1h[s0 * 32 + lane]);
        float2 v1 = __half22float2(g_h1h[s1 * 32 + lane]);
        float2 v2 = __half22float2(g_h1h[s2 * 32 + lane]);
        float2 v3 = __half22float2(g_h1h[s3 * 32 + lane]);
        float e0 = __expf(lrelu(t0)), e1 = __expf(lrelu(t1));
        float e2 = __expf(lrelu(t2)), e3 = __expf(lrelu(t3));
        den += (e0 + e1) + (e2 + e3);
        ax += e0 * v0.x + e1 * v1.x + e2 * v2.x + e3 * v3.x;
        ay += e0 * v0.y + e1 * v1.y + e2 * v2.y + e3 * v3.y;
    }
    for (; j < deg; j++) {
        int s0 = g_srcs[rs + j];
        float t0 = g_as1[s0 * 4 + head] + adv;
        float2 v0 = __half22float2(g_h1h[s0 * 32 + lane]);
        float e0 = __expf(lrelu(t0));
        den += e0;
        ax += e0 * v0.x;
        ay += e0 * v0.y;
    }
    float inv = 1.f / (den + 1e-16f);
    float2 o;
    o.x = ax * inv;
    o.y = ay * inv;
    ((float2*)g_agg1)[n * 32 + lane] = o;
}

// ---------------- layer-2 GEMM: h2 = relu(agg1 + b1) @ W2 (fp16 out) + dots (1 head) ----------------
__global__ void k_gemm2(const float* __restrict__ W2, const float* __restrict__ b1,
                        const float* __restrict__ a_src, const float* __restrict__ a_dst) {
    __shared__ float2 Wsh[HID * 32];
    int tid = threadIdx.x;
    for (int i = tid; i < HID * 32; i += 256) Wsh[i] = ((const float2*)W2)[i];
    __syncthreads();

    int lane = tid & 31, w = tid >> 5;
    int r0 = (blockIdx.x * 8 + w) * 4;
    float b0 = __ldg(&b1[2 * lane]), b1v = __ldg(&b1[2 * lane + 1]);

    float2 xr[4];
#pragma unroll
    for (int i = 0; i < 4; i++) {
        float2 v = ((const float2*)g_agg1)[(r0 + i) * 32 + lane];
        xr[i].x = fmaxf(v.x + b0, 0.f);
        xr[i].y = fmaxf(v.y + b1v, 0.f);
    }

    float acc0[4] = {}, acc1[4] = {};
#pragma unroll
    for (int k = 0; k < HID; k++) {
        float2 wv = Wsh[k * 32 + lane];
#pragma unroll
        for (int i = 0; i < 4; i++) {
            float xk = __shfl_sync(0xffffffffu, (k & 1) ? xr[i].y : xr[i].x, k >> 1);
            acc0[i] += xk * wv.x;
            acc1[i] += xk * wv.y;
        }
    }

    float s0 = __ldg(&a_src[2 * lane]), s1 = __ldg(&a_src[2 * lane + 1]);
    float d0 = __ldg(&a_dst[2 * lane]), d1 = __ldg(&a_dst[2 * lane + 1]);

#pragma unroll
    for (int i = 0; i < 4; i++) {
        int row = r0 + i;
        g_h2h[row * 32 + lane] = __floats2half2_rn(acc0[i], acc1[i]);
        float pa = acc0[i] * s0 + acc1[i] * s1;
        float pd = acc0[i] * d0 + acc1[i] * d1;
#pragma unroll
        for (int off = 16; off; off >>= 1) {
            pa += __shfl_xor_sync(0xffffffffu, pa, off);
            pd += __shfl_xor_sync(0xffffffffu, pd, off);
        }
        if (lane == 0) {
            g_as2[row] = pa;
            g_ad2[row] = pd;
        }
    }
}

// ---------------- layer-2 gather aggregation fused with final projection ----------------
__global__ void k_agg2f(const float* __restrict__ b2, const float* __restrict__ Wc,
                        const float* __restrict__ bc, float* __restrict__ out) {
    int n = blockIdx.x * 8 + (threadIdx.x >> 5);
    if (n >= NN) return;
    int lane = threadIdx.x & 31;

    int rs = g_rs[n];
    int deg = g_cnt[n];
    float adv = g_ad2[n];

    float ax = 0.f, ay = 0.f, den = 0.f;

    int j = 0;
    for (; j + 4 <= deg; j += 4) {
        int s0 = g_srcs[rs + j],     s1 = g_srcs[rs + j + 1];
        int s2 = g_srcs[rs + j + 2], s3 = g_srcs[rs + j + 3];
        float t0 = g_as2[s0] + adv, t1 = g_as2[s1] + adv;
        float t2 = g_as2[s2] + adv, t3 = g_as2[s3] + adv;
        float2 v0 = __half22float2(g_h2h[s0 * 32 + lane]);
        float2 v1 = __half22float2(g_h2h[s1 * 32 + lane]);
        float2 v2 = __half22float2(g_h2h[s2 * 32 + lane]);
        float2 v3 = __half22float2(g_h2h[s3 * 32 + lane]);
        float e0 = __expf(lrelu(t0)), e1 = __expf(lrelu(t1));
        float e2 = __expf(lrelu(t2)), e3 = __expf(lrelu(t3));
        den += (e0 + e1) + (e2 + e3);
        ax += e0 * v0.x + e1 * v1.x + e2 * v2.x + e3 * v3.x;
        ay += e0 * v0.y + e1 * v1.y + e2 * v2.y + e3 * v3.y;
    }
    for (; j < deg; j++) {
        int s0 = g_srcs[rs + j];
        float t0 = g_as2[s0] + adv;
        float2 v0 = __half22float2(g_h2h[s0 * 32 + lane]);
        float e0 = __expf(lrelu(t0));
        den += e0;
        ax += e0 * v0.x;
        ay += e0 * v0.y;
    }
    float inv = 1.f / (den + 1e-16f);
    float v = fmaxf(ax * inv + __ldg(&b2[2 * lane]), 0.f) * __ldg(&Wc[2 * lane])
            + fmaxf(ay * inv + __ldg(&b2[2 * lane + 1]), 0.f) * __ldg(&Wc[2 * lane + 1]);
#pragma unroll
    for (int off = 16; off; off >>= 1) v += __shfl_xor_sync(0xffffffffu, v, off);
    if (lane == 0) out[n] = v + __ldg(&bc[0]);
}

extern "C" void kernel_launch(void* const* d_in, const int* in_sizes, int n_in,
                              void* d_out, int out_size) {
    const float* x      = (const float*)d_in[0];
    const int* ei       = (const int*)d_in[1];   // JAX x64 disabled -> int32
    const float* W1     = (const float*)d_in[2];
    const float* a_src1 = (const float*)d_in[3];
    const float* a_dst1 = (const float*)d_in[4];
    const float* b1     = (const float*)d_in[5];
    const float* W2     = (const float*)d_in[6];
    const float* a_src2 = (const float*)d_in[7];
    const float* a_dst2 = (const float*)d_in[8];
    const float* b2     = (const float*)d_in[9];
    const float* Wc     = (const float*)d_in[10];
    const float* bc     = (const float*)d_in[11];
    float* out          = (float*)d_out;
    (void)in_sizes; (void)n_in; (void)out_size;

    // CSR build, with gemm1 moved to slot 4 (independent of CSR) so the ncu
    // -s5-c1 sample (deterministically the 4th launch) profiles it.
    k_zero_cnt<<<(NN + 255) / 256, 256>>>();            // 1
    k_hist<<<(EE + 255) / 256, 256>>>(ei);              // 2
    k_scan<<<1, 1024>>>();                              // 3
    k_gemm1<<<3125, 256>>>(x, W1, a_src1, a_dst1);      // 4  <- ncu sample
    k_fill<<<(EE + 255) / 256, 256>>>(ei);              // 5

    k_agg1<<<12500, 256>>>();                           // 6
    k_gemm2<<<3125, 256>>>(W2, b1, a_src2, a_dst2);     // 7
    k_agg2f<<<12500, 256>>>(b2, Wc, bc, out);           // 8
}

// round 7
// speedup vs baseline: 1.2659x; 1.2659x over previous
#include <cuda_runtime.h>
#include <cuda_fp16.h>

#define NN 100000
#define EE 1600000
#define FIN 128
#define HID 64

// ---- scratch (static __device__ — no allocation) ----
__device__ __align__(16) __half2 g_h1h[NN * 32];  // h1, fp16, feature pairs
__device__ __align__(16) __half2 g_h2h[NN * 32];  // h2, fp16
__device__ __align__(16) float g_as1[NN * 4];
__device__ __align__(16) float g_ad1[NN * 4];
__device__ __align__(16) float g_agg1[NN * HID];
__device__ __align__(16) float g_as2[NN];
__device__ __align__(16) float g_ad2[NN];
__device__ int g_cnt[NN];    // degree by dst (zero at load; re-zeroed by agg2f each call)
__device__ int g_rs[NN];     // CSR row starts (unordered ranges)
__device__ int g_cur[NN];    // fill cursors
__device__ int g_srcs[EE];   // CSR: src per incident edge, grouped by dst
__device__ int g_total;      // range-allocation cursor (reset by k_fill each call)

__device__ __forceinline__ float lrelu(float t) { return t > 0.f ? t : 0.2f * t; }

// ---------------- layer-1 GEMM (+ fused degree histogram) ----------------
// h1 = x @ W1 (fp16 out) + per-head attention dots.
// Lane owns adjacent feature pair (2*lane, 2*lane+1); head = lane>>3.
__global__ void k_gemm1h(const float* __restrict__ x, const float* __restrict__ W1,
                         const float* __restrict__ a_src, const float* __restrict__ a_dst,
                         const int* __restrict__ ei) {
    __shared__ float2 Wsh[FIN * 32];
    int tid = threadIdx.x;

    // fused histogram: exactly 2 edges per thread (3125*512 == EE)
    {
        int e = blockIdx.x * 512 + tid;
        atomicAdd(&g_cnt[__ldg(&ei[EE + e])], 1);
        atomicAdd(&g_cnt[__ldg(&ei[EE + e + 256])], 1);
    }

    for (int i = tid; i < FIN * 32; i += 256) Wsh[i] = ((const float2*)W1)[i];
    __syncthreads();

    int lane = tid & 31, w = tid >> 5;
    int r0 = (blockIdx.x * 8 + w) * 4;

    float xr[4][4];
#pragma unroll
    for (int i = 0; i < 4; i++)
#pragma unroll
        for (int j = 0; j < 4; j++)
            xr[i][j] = x[(r0 + i) * FIN + 32 * j + lane];

    float acc0[4] = {}, acc1[4] = {};
#pragma unroll
    for (int k = 0; k < FIN; k++) {
        float2 wv = Wsh[k * 32 + lane];
#pragma unroll
        for (int i = 0; i < 4; i++) {
            float xk = __shfl_sync(0xffffffffu, xr[i][k >> 5], k & 31);
            acc0[i] += xk * wv.x;
            acc1[i] += xk * wv.y;
        }
    }

    float s0 = __ldg(&a_src[2 * lane]), s1 = __ldg(&a_src[2 * lane + 1]);
    float d0 = __ldg(&a_dst[2 * lane]), d1 = __ldg(&a_dst[2 * lane + 1]);

#pragma unroll
    for (int i = 0; i < 4; i++) {
        int row = r0 + i;
        g_h1h[row * 32 + lane] = __floats2half2_rn(acc0[i], acc1[i]);
        float pa = acc0[i] * s0 + acc1[i] * s1;
        float pd = acc0[i] * d0 + acc1[i] * d1;
#pragma unroll
        for (int off = 4; off; off >>= 1) {
            pa += __shfl_xor_sync(0xffffffffu, pa, off);
            pd += __shfl_xor_sync(0xffffffffu, pd, off);
        }
        if ((lane & 7) == 0) {
            g_as1[row * 4 + (lane >> 3)] = pa;
            g_ad1[row * 4 + (lane >> 3)] = pd;
        }
    }
}

// ---------------- CSR range allocation (no ordered scan needed) ----------------
__global__ void k_alloc() {
    int i = blockIdx.x * blockDim.x + threadIdx.x;
    int lane = threadIdx.x & 31;
    int c = (i < NN) ? g_cnt[i] : 0;
    int s = c;
#pragma unroll
    for (int off = 1; off < 32; off <<= 1) {
        int t = __shfl_up_sync(0xffffffffu, s, off);
        if (lane >= off) s += t;
    }
    int wtot = __shfl_sync(0xffffffffu, s, 31);
    int base = 0;
    if (lane == 31) base = atomicAdd(&g_total, wtot);
    base = __shfl_sync(0xffffffffu, base, 31);
    if (i < NN) {
        int r = base + s - c;
        g_rs[i] = r;
        g_cur[i] = r;
    }
}

__global__ void k_fill(const int* __restrict__ ei) {
    int e = blockIdx.x * blockDim.x + threadIdx.x;
    if (e == 0) g_total = 0;  // reset allocation cursor for the next call
    if (e < EE) {
        int s = __ldg(&ei[e]);
        int d = __ldg(&ei[EE + e]);
        int p = atomicAdd(&g_cur[d], 1);
        g_srcs[p] = s;
    }
}

// ---------------- layer-1 gather aggregation: one warp per dst node ----------------
__global__ void k_agg1() {
    int n = blockIdx.x * 8 + (threadIdx.x >> 5);
    if (n >= NN) return;
    int lane = threadIdx.x & 31;
    int head = lane >> 3;

    int rs = g_rs[n];
    int deg = g_cnt[n];
    float adv = g_ad1[n * 4 + head];

    float ax = 0.f, ay = 0.f, den = 0.f;

    int j = 0;
    for (; j + 4 <= deg; j += 4) {
        int s0 = g_srcs[rs + j],     s1 = g_srcs[rs + j + 1];
        int s2 = g_srcs[rs + j + 2], s3 = g_srcs[rs + j + 3];
        float t0 = g_as1[s0 * 4 + head] + adv;
        float t1 = g_as1[s1 * 4 + head] + adv;
        float t2 = g_as1[s2 * 4 + head] + adv;
        float t3 = g_as1[s3 * 4 + head] + adv;
        float2 v0 = __half22float2(g_h1h[s0 * 32 + lane]);
        float2 v1 = __half22float2(g_h1h[s1 * 32 + lane]);
        float2 v2 = __half22float2(g_h1h[s2 * 32 + lane]);
        float2 v3 = __half22float2(g_h1h[s3 * 32 + lane]);
        float e0 = __expf(lrelu(t0)), e1 = __expf(lrelu(t1));
        float e2 = __expf(lrelu(t2)), e3 = __expf(lrelu(t3));
        den += (e0 + e1) + (e2 + e3);
        ax += e0 * v0.x + e1 * v1.x + e2 * v2.x + e3 * v3.x;
        ay += e0 * v0.y + e1 * v1.y + e2 * v2.y + e3 * v3.y;
    }
    for (; j < deg; j++) {
        int s0 = g_srcs[rs + j];
        float t0 = g_as1[s0 * 4 + head] + adv;
        float2 v0 = __half22float2(g_h1h[s0 * 32 + lane]);
        float e0 = __expf(lrelu(t0));
        den += e0;
        ax += e0 * v0.x;
        ay += e0 * v0.y;
    }
    float inv = 1.f / (den + 1e-16f);
    float2 o;
    o.x = ax * inv;
    o.y = ay * inv;
    ((float2*)g_agg1)[n * 32 + lane] = o;
}

// ---------------- layer-2 GEMM: h2 = relu(agg1 + b1) @ W2 (fp16 out) + dots (1 head) ----------------
__global__ void k_gemm2(const float* __restrict__ W2, const float* __restrict__ b1,
                        const float* __restrict__ a_src, const float* __restrict__ a_dst) {
    __shared__ float2 Wsh[HID * 32];
    int tid = threadIdx.x;
    for (int i = tid; i < HID * 32; i += 256) Wsh[i] = ((const float2*)W2)[i];
    __syncthreads();

    int lane = tid & 31, w = tid >> 5;
    int r0 = (blockIdx.x * 8 + w) * 4;
    float b0 = __ldg(&b1[2 * lane]), b1v = __ldg(&b1[2 * lane + 1]);

    float2 xr[4];
#pragma unroll
    for (int i = 0; i < 4; i++) {
        float2 v = ((const float2*)g_agg1)[(r0 + i) * 32 + lane];
        xr[i].x = fmaxf(v.x + b0, 0.f);
        xr[i].y = fmaxf(v.y + b1v, 0.f);
    }

    float acc0[4] = {}, acc1[4] = {};
#pragma unroll
    for (int k = 0; k < HID; k++) {
        float2 wv = Wsh[k * 32 + lane];
#pragma unroll
        for (int i = 0; i < 4; i++) {
            float xk = __shfl_sync(0xffffffffu, (k & 1) ? xr[i].y : xr[i].x, k >> 1);
            acc0[i] += xk * wv.x;
            acc1[i] += xk * wv.y;
        }
    }

    float s0 = __ldg(&a_src[2 * lane]), s1 = __ldg(&a_src[2 * lane + 1]);
    float d0 = __ldg(&a_dst[2 * lane]), d1 = __ldg(&a_dst[2 * lane + 1]);

#pragma unroll
    for (int i = 0; i < 4; i++) {
        int row = r0 + i;
        g_h2h[row * 32 + lane] = __floats2half2_rn(acc0[i], acc1[i]);
        float pa = acc0[i] * s0 + acc1[i] * s1;
        float pd = acc0[i] * d0 + acc1[i] * d1;
#pragma unroll
        for (int off = 16; off; off >>= 1) {
            pa += __shfl_xor_sync(0xffffffffu, pa, off);
            pd += __shfl_xor_sync(0xffffffffu, pd, off);
        }
        if (lane == 0) {
            g_as2[row] = pa;
            g_ad2[row] = pd;
        }
    }
}

// ---------------- layer-2 gather aggregation fused with final projection ----------------
__global__ void k_agg2f(const float* __restrict__ b2, const float* __restrict__ Wc,
                        const float* __restrict__ bc, float* __restrict__ out) {
    int n = blockIdx.x * 8 + (threadIdx.x >> 5);
    if (n >= NN) return;
    int lane = threadIdx.x & 31;

    int rs = g_rs[n];
    int deg = g_cnt[n];
    float adv = g_ad2[n];

    float ax = 0.f, ay = 0.f, den = 0.f;

    int j = 0;
    for (; j + 4 <= deg; j += 4) {
        int s0 = g_srcs[rs + j],     s1 = g_srcs[rs + j + 1];
        int s2 = g_srcs[rs + j + 2], s3 = g_srcs[rs + j + 3];
        float t0 = g_as2[s0] + adv, t1 = g_as2[s1] + adv;
        float t2 = g_as2[s2] + adv, t3 = g_as2[s3] + adv;
        float2 v0 = __half22float2(g_h2h[s0 * 32 + lane]);
        float2 v1 = __half22float2(g_h2h[s1 * 32 + lane]);
        float2 v2 = __half22float2(g_h2h[s2 * 32 + lane]);
        float2 v3 = __half22float2(g_h2h[s3 * 32 + lane]);
        float e0 = __expf(lrelu(t0)), e1 = __expf(lrelu(t1));
        float e2 = __expf(lrelu(t2)), e3 = __expf(lrelu(t3));
        den += (e0 + e1) + (e2 + e3);
        ax += e0 * v0.x + e1 * v1.x + e2 * v2.x + e3 * v3.x;
        ay += e0 * v0.y + e1 * v1.y + e2 * v2.y + e3 * v3.y;
    }
    for (; j < deg; j++) {
        int s0 = g_srcs[rs + j];
        float t0 = g_as2[s0] + adv;
        float2 v0 = __half22float2(g_h2h[s0 * 32 + lane]);
        float e0 = __expf(lrelu(t0));
        den += e0;
        ax += e0 * v0.x;
        ay += e0 * v0.y;
    }
    float inv = 1.f / (den + 1e-16f);
    float v = fmaxf(ax * inv + __ldg(&b2[2 * lane]), 0.f) * __ldg(&Wc[2 * lane])
            + fmaxf(ay * inv + __ldg(&b2[2 * lane + 1]), 0.f) * __ldg(&Wc[2 * lane + 1]);
#pragma unroll
    for (int off = 16; off; off >>= 1) v += __shfl_xor_sync(0xffffffffu, v, off);
    if (lane == 0) {
        out[n] = v + __ldg(&bc[0]);
        g_cnt[n] = 0;  // restore invariant: g_cnt zero for the next call's histogram
    }
}

extern "C" void kernel_launch(void* const* d_in, const int* in_sizes, int n_in,
                              void* d_out, int out_size) {
    const float* x      = (const float*)d_in[0];
    const int* ei       = (const int*)d_in[1];   // JAX x64 disabled -> int32
    const float* W1     = (const float*)d_in[2];
    const float* a_src1 = (const float*)d_in[3];
    const float* a_dst1 = (const float*)d_in[4];
    const float* b1     = (const float*)d_in[5];
    const float* W2     = (const float*)d_in[6];
    const float* a_src2 = (const float*)d_in[7];
    const float* a_dst2 = (const float*)d_in[8];
    const float* b2     = (const float*)d_in[9];
    const float* Wc     = (const float*)d_in[10];
    const float* bc     = (const float*)d_in[11];
    float* out          = (float*)d_out;
    (void)in_sizes; (void)n_in; (void)out_size;

    k_gemm1h<<<3125, 256>>>(x, W1, a_src1, a_dst1, ei);  // 1: GEMM1 + degree hist
    k_alloc<<<(NN + 255) / 256, 256>>>();                // 2: CSR range alloc
    k_fill<<<(EE + 255) / 256, 256>>>(ei);               // 3: CSR fill
    k_agg1<<<12500, 256>>>();                            // 4: <- ncu sample
    k_gemm2<<<3125, 256>>>(W2, b1, a_src2, a_dst2);      // 5
    k_agg2f<<<12500, 256>>>(b2, Wc, bc, out);            // 6
}